// round 16
// baseline (speedup 1.0000x reference)
#include <cuda_runtime.h>
#include <cuda_fp16.h>
#include <math.h>
#include <stdint.h>

#define BB 8
#define CC 64
#define HH 256
#define WW 256
#define THETA 0.7f

#define PX   32              // pixels per CTA
#define NCOL 34              // staged cols: x0-1 .. x0+32
#define CPAD 72              // padded channels -> 144B rows (conflict-free ldmatrix)
#define RAW_B   (4 * NCOL * CPAD * 2)    // 19584: rows 0..2 input + row 3 edge, fp16
#define SMEM_BYTES RAW_B                 // 19584 -> 8 CTAs/SM (reg-limited at 32)

__device__ float g_pooled[BB * CC];
__device__ float g_attn[BB * CC];
// B (fp16) in mma-fragment order: [tap][o2][k2][np][ki][lane] -> uint4
__device__ uint4 g_Bf[10 * 2 * 2 * 2 * 2 * 32];

// ---------------- helpers ----------------
__device__ __forceinline__ uint32_t smem_u32(const void* p) {
    uint32_t a;
    asm("{ .reg .u64 t; cvta.to.shared.u64 t, %1; cvt.u32.u64 %0, t; }" : "=r"(a) : "l"(p));
    return a;
}
#define LDM4(r0, r1, r2, r3, a) \
    asm volatile("ldmatrix.sync.aligned.m8n8.x4.shared.b16 {%0,%1,%2,%3}, [%4];" \
                 : "=r"(r0), "=r"(r1), "=r"(r2), "=r"(r3) : "r"(a))
#define MMA(c, a, b) \
    asm volatile("mma.sync.aligned.m16n8k16.row.col.f32.f16.f16.f32 " \
                 "{%0,%1,%2,%3},{%4,%5,%6,%7},{%8,%9},{%0,%1,%2,%3};" \
                 : "+f"((c)[0]), "+f"((c)[1]), "+f"((c)[2]), "+f"((c)[3]) \
                 : "r"((a)[0]), "r"((a)[1]), "r"((a)[2]), "r"((a)[3]), \
                   "r"((b)[0]), "r"((b)[1]))

// ---------------------------------------------------------------------------
// Kernel 0: prepack B (prescaled fp16) in mma-fragment order; zero GAP accum.
// tap t<9: w = THETA * Wc[oc][c][t/3][t%3];  t==9: w = (1-THETA) * We[oc][c]
// ---------------------------------------------------------------------------
__global__ void prepack_kernel(const float* __restrict__ Wc,
                               const float* __restrict__ We) {
    int idx = blockIdx.x * blockDim.x + threadIdx.x;   // 6144 threads
    if (idx < BB * CC) g_pooled[idx] = 0.0f;
    if (idx >= 10 * 512) return;
    int lane = idx & 31;
    int ki   = (idx >> 5) & 1;
    int np   = (idx >> 6) & 1;
    int k2   = (idx >> 7) & 1;
    int o2   = (idx >> 8) & 1;
    int tap  = idx >> 9;

    uint32_t regs[4];
#pragma unroll
    for (int r = 0; r < 4; r++) {
        int oc    = o2 * 32 + np * 16 + (r >> 1) * 8 + (lane >> 2);
        int kbase = k2 * 32 + ki * 16 + (r & 1) * 8 + 2 * (lane & 3);
        uint32_t v = 0;
#pragma unroll
        for (int e = 0; e < 2; e++) {
            int c = kbase + e;
            float w = (tap < 9)
                ? THETA * Wc[((oc * CC + c) * 3 + tap / 3) * 3 + (tap % 3)]
                : (1.0f - THETA) * We[oc * CC + c];
            v |= (uint32_t)__half_as_ushort(__float2half_rn(w)) << (e * 16);
        }
        regs[r] = v;
    }
    g_Bf[idx] = make_uint4(regs[0], regs[1], regs[2], regs[3]);
}

// ---------------------------------------------------------------------------
// Kernel 1: HMMA implicit-GEMM conv, single-pass fp16, barrier-free tap loop.
// Grid (8, 256, 8), 256 threads, 8 CTAs/SM (64 warps/SM).
// Warp w: pxh=w&1 (16-px half), ocq=w>>1 (16-oc quarter). Full K=64 per warp
// (no K-split, no exchange). Acc: 8 fp32 regs (2 ni x 4).
// ---------------------------------------------------------------------------
__global__ void __launch_bounds__(256, 8)
conv_kernel(const float* __restrict__ x,
            const float* __restrict__ b_conv,
            float* __restrict__ out) {
    extern __shared__ __align__(16) unsigned char smem[];
    __shared__ float s_red[CC];

    unsigned short* raw = (unsigned short*)smem;
    const uint32_t sbase = smem_u32(smem);

    const int tid  = threadIdx.x;
    const int lane = tid & 31;
    const int wid  = tid >> 5;
    const int x0   = blockIdx.x * PX;
    const int y    = blockIdx.y;
    const int b    = blockIdx.z;

    if (tid < CC) s_red[tid] = 0.0f;

    // ---- stage input rows y-1..y+1 as fp16, layout [r][col][c]
    const float* xb = x + (size_t)b * CC * HH * WW;
    for (int idx = tid; idx < CC * 3 * NCOL; idx += 256) {
        int c   = idx / (3 * NCOL);
        int rem = idx % (3 * NCOL);
        int r   = rem / NCOL;
        int col = rem % NCOL;
        int gy  = y - 1 + r;
        int gx  = x0 - 1 + col;
        float v = 0.0f;
        if ((unsigned)gy < HH && (unsigned)gx < WW)
            v = xb[(c * HH + gy) * WW + gx];
        raw[(r * NCOL + col) * CPAD + c] = __half_as_ushort(__float2half_rn(v));
    }
    __syncthreads();

    // ---- edge row (row 3): |x(y-1) - x(y+1)| from staged fp16 values
    for (int idx = tid; idx < NCOL * CC; idx += 256) {
        int col = idx >> 6;
        int c   = idx & 63;
        float a0 = __half2float(__ushort_as_half(raw[(0 * NCOL + col) * CPAD + c]));
        float a2 = __half2float(__ushort_as_half(raw[(2 * NCOL + col) * CPAD + c]));
        raw[(3 * NCOL + col) * CPAD + c] =
            __half_as_ushort(__float2half_rn(fabsf(a0 - a2)));
    }
    __syncthreads();   // raw tile final — no more barriers until epilogue

    float acc[2][4];
#pragma unroll
    for (int ni = 0; ni < 2; ni++)
#pragma unroll
        for (int r = 0; r < 4; r++) acc[ni][r] = 0.0f;

    const int pxh = wid & 1;
    const int ocq = wid >> 1;                 // 0..3 -> oc quarter of 16
    const int px0 = pxh * 16;
    const int arow_lane = lane & 15;
    const int acol_lane = (lane >> 4) * 8;

    // per-warp B table base: [tap][o2][k2][np][ki][lane]; o2=ocq>>1, np=ocq&1
    const uint4* Bw = g_Bf + (ocq >> 1) * 256 + (ocq & 1) * 64 + lane;

#pragma unroll
    for (int t = 0; t < 10; t++) {
        const int dy = (t < 9) ? t / 3 : 3;
        const int dx = (t < 9) ? t % 3 : 1;
        const int abase = (dy * NCOL + px0 + dx + arow_lane) * CPAD + acol_lane;

        // K=64: 4 chunks of k16, interleaved to keep live regs minimal
#pragma unroll
        for (int kk = 0; kk < 4; kk++) {       // kk = k2*2 + ki
            uint32_t A[4];
            LDM4(A[0], A[1], A[2], A[3],
                 sbase + (uint32_t)((abase + kk * 16) * 2));
            uint4 v = __ldg(Bw + t * 512 + (kk >> 1) * 128 + (kk & 1) * 32);
            uint32_t B0[2] = {v.x, v.y};
            uint32_t B1[2] = {v.z, v.w};
            MMA(acc[0], A, B0);
            MMA(acc[1], A, B1);
        }
    }

    // ---- epilogue: bias, store, GAP (all 8 warps, full-K accumulators)
#pragma unroll
    for (int ni = 0; ni < 2; ni++) {
        const int oca = ocq * 16 + ni * 8 + 2 * (lane & 3);
        const float ba = THETA * __ldg(&b_conv[oca]);
        const float bb = THETA * __ldg(&b_conv[oca + 1]);
        float d0 = acc[ni][0] + ba;
        float d1 = acc[ni][1] + bb;
        float d2 = acc[ni][2] + ba;
        float d3 = acc[ni][3] + bb;
        int pxg = x0 + px0 + (lane >> 2);
        size_t base = ((size_t)b * CC + oca) * (size_t)(HH * WW)
                    + (size_t)y * WW + pxg;
        out[base]               = d0;
        out[base + HH * WW]     = d1;
        out[base + 8]           = d2;
        out[base + HH * WW + 8] = d3;
        float sA = d0 + d2;
        float sB = d1 + d3;
#pragma unroll
        for (int s = 4; s < 32; s <<= 1) {
            sA += __shfl_xor_sync(0xffffffffu, sA, s);
            sB += __shfl_xor_sync(0xffffffffu, sB, s);
        }
        if (lane < 4) {
            atomicAdd(&s_red[oca], sA);
            atomicAdd(&s_red[oca + 1], sB);
        }
    }
    __syncthreads();
    if (tid < CC) atomicAdd(&g_pooled[b * CC + tid], s_red[tid]);
}

// ---------------------------------------------------------------------------
// Kernel 2: SE attention (GAP -> 1x1 -> ReLU -> 1x1 -> sigmoid), 1 block
// ---------------------------------------------------------------------------
__global__ void attn_kernel(const float* __restrict__ W1, const float* __restrict__ b1,
                            const float* __restrict__ W2, const float* __restrict__ b2) {
    __shared__ float sh[BB * 8];
    const int t = threadIdx.x;
    if (t < BB * 8) {
        int b = t >> 3, r = t & 7;
        float s = b1[r];
        const float inv = 1.0f / (float)(HH * WW);
#pragma unroll
        for (int c = 0; c < CC; c++)
            s += (g_pooled[b * CC + c] * inv) * W1[r * CC + c];
        sh[t] = fmaxf(s, 0.0f);
    }
    __syncthreads();
    for (int idx = t; idx < BB * CC; idx += 256) {
        int b = idx >> 6, o = idx & 63;
        float s = b2[o];
#pragma unroll
        for (int r = 0; r < 8; r++)
            s += sh[b * 8 + r] * W2[o * 8 + r];
        g_attn[idx] = 1.0f / (1.0f + expf(-s));
    }
}

// ---------------------------------------------------------------------------
// Kernel 3: scale output by per-(b,c) attention (float4 grid)
// ---------------------------------------------------------------------------
__global__ void scale_kernel(float* __restrict__ out) {
    int i = blockIdx.x * blockDim.x + threadIdx.x;
    float4 v = ((float4*)out)[i];
    float a = g_attn[i >> 14];           // 16384 float4 per (b,c)
    v.x *= a; v.y *= a; v.z *= a; v.w *= a;
    ((float4*)out)[i] = v;
}

// ---------------------------------------------------------------------------
extern "C" void kernel_launch(void* const* d_in, const int* in_sizes, int n_in,
                              void* d_out, int out_size) {
    const float* x  = (const float*)d_in[0];
    const float* Wc = (const float*)d_in[1];
    const float* bc = (const float*)d_in[2];
    const float* We = (const float*)d_in[3];
    const float* W1 = (const float*)d_in[4];
    const float* b1 = (const float*)d_in[5];
    const float* W2 = (const float*)d_in[6];
    const float* b2 = (const float*)d_in[7];
    float* out = (float*)d_out;

    cudaFuncSetAttribute(conv_kernel, cudaFuncAttributeMaxDynamicSharedMemorySize, SMEM_BYTES);

    prepack_kernel<<<24, 256>>>(Wc, We);

    dim3 grid(WW / PX, HH, BB);
    conv_kernel<<<grid, 256, SMEM_BYTES>>>(x, bc, out);

    attn_kernel<<<1, 256>>>(W1, b1, W2, b2);

    scale_kernel<<<(BB * CC * HH * WW / 4) / 256, 256>>>(out);
}

// round 17
// speedup vs baseline: 1.0990x; 1.0990x over previous
#include <cuda_runtime.h>
#include <cuda_fp16.h>
#include <math.h>
#include <stdint.h>

#define BB 8
#define CC 64
#define HH 256
#define WW 256
#define THETA 0.7f

#define PX   32              // pixels per CTA
#define NCOL 34              // staged cols: x0-1 .. x0+32
#define CPAD 72              // padded channels -> 144B rows (conflict-free ldmatrix)
#define RAW_B   (4 * NCOL * CPAD * 2)    // 19584: rows 0..2 input + row 3 edge, fp16
#define EX_OFF  RAW_B                    // K-split exchange (8KB)
#define SMEM_BYTES (EX_OFF + 8192)       // 27776 -> 6 CTAs/SM (reg-limited)

__device__ float g_pooled[BB * CC];
__device__ float g_attn[BB * CC];
// B (fp16) in mma-fragment order: [tap][o2][k2][np][ki][lane] -> uint4
__device__ uint4 g_Bf[10 * 2 * 2 * 2 * 2 * 32];
// fp16 intermediate for combined (bias-free), NCHW
__device__ __half g_comb[(size_t)BB * CC * HH * WW];

// ---------------- helpers ----------------
__device__ __forceinline__ uint32_t smem_u32(const void* p) {
    uint32_t a;
    asm("{ .reg .u64 t; cvta.to.shared.u64 t, %1; cvt.u32.u64 %0, t; }" : "=r"(a) : "l"(p));
    return a;
}
#define LDM4(r0, r1, r2, r3, a) \
    asm volatile("ldmatrix.sync.aligned.m8n8.x4.shared.b16 {%0,%1,%2,%3}, [%4];" \
                 : "=r"(r0), "=r"(r1), "=r"(r2), "=r"(r3) : "r"(a))
#define MMA(c, a, b) \
    asm volatile("mma.sync.aligned.m16n8k16.row.col.f32.f16.f16.f32 " \
                 "{%0,%1,%2,%3},{%4,%5,%6,%7},{%8,%9},{%0,%1,%2,%3};" \
                 : "+f"((c)[0]), "+f"((c)[1]), "+f"((c)[2]), "+f"((c)[3]) \
                 : "r"((a)[0]), "r"((a)[1]), "r"((a)[2]), "r"((a)[3]), \
                   "r"((b)[0]), "r"((b)[1]))

// ---------------------------------------------------------------------------
// Kernel 0: prepack B (prescaled fp16) in mma-fragment order; zero GAP accum.
// tap t<9: w = THETA * Wc[oc][c][t/3][t%3];  t==9: w = (1-THETA) * We[oc][c]
// ---------------------------------------------------------------------------
__global__ void prepack_kernel(const float* __restrict__ Wc,
                               const float* __restrict__ We) {
    int idx = blockIdx.x * blockDim.x + threadIdx.x;   // 6144 threads
    if (idx < BB * CC) g_pooled[idx] = 0.0f;
    if (idx >= 10 * 512) return;
    int lane = idx & 31;
    int ki   = (idx >> 5) & 1;
    int np   = (idx >> 6) & 1;
    int k2   = (idx >> 7) & 1;
    int o2   = (idx >> 8) & 1;
    int tap  = idx >> 9;

    uint32_t regs[4];
#pragma unroll
    for (int r = 0; r < 4; r++) {
        int oc    = o2 * 32 + np * 16 + (r >> 1) * 8 + (lane >> 2);
        int kbase = k2 * 32 + ki * 16 + (r & 1) * 8 + 2 * (lane & 3);
        uint32_t v = 0;
#pragma unroll
        for (int e = 0; e < 2; e++) {
            int c = kbase + e;
            float w = (tap < 9)
                ? THETA * Wc[((oc * CC + c) * 3 + tap / 3) * 3 + (tap % 3)]
                : (1.0f - THETA) * We[oc * CC + c];
            v |= (uint32_t)__half_as_ushort(__float2half_rn(w)) << (e * 16);
        }
        regs[r] = v;
    }
    g_Bf[idx] = make_uint4(regs[0], regs[1], regs[2], regs[3]);
}

// ---------------------------------------------------------------------------
// Kernel 1: HMMA implicit-GEMM conv (R15 structure), fp16 single-pass,
// barrier-free tap loop. Grid (8, 256, 8), 256 threads, 6 CTAs/SM.
// Warp w: p=(w>>2)&1 px half, o=(w>>1)&1 oc half, kh=w&1 K half.
// Stores bias-free acc as fp16 to g_comb; GAP partials bias-free.
// ---------------------------------------------------------------------------
__global__ void __launch_bounds__(256, 6)
conv_kernel(const float* __restrict__ x) {
    extern __shared__ __align__(16) unsigned char smem[];
    __shared__ float s_red[CC];

    unsigned short* raw = (unsigned short*)smem;
    const uint32_t sbase = smem_u32(smem);

    const int tid  = threadIdx.x;
    const int lane = tid & 31;
    const int wid  = tid >> 5;
    const int x0   = blockIdx.x * PX;
    const int y    = blockIdx.y;
    const int b    = blockIdx.z;

    if (tid < CC) s_red[tid] = 0.0f;

    // ---- stage input rows y-1..y+1 as fp16, layout [r][col][c]
    const float* xb = x + (size_t)b * CC * HH * WW;
    for (int idx = tid; idx < CC * 3 * NCOL; idx += 256) {
        int c   = idx / (3 * NCOL);
        int rem = idx % (3 * NCOL);
        int r   = rem / NCOL;
        int col = rem % NCOL;
        int gy  = y - 1 + r;
        int gx  = x0 - 1 + col;
        float v = 0.0f;
        if ((unsigned)gy < HH && (unsigned)gx < WW)
            v = xb[(c * HH + gy) * WW + gx];
        raw[(r * NCOL + col) * CPAD + c] = __half_as_ushort(__float2half_rn(v));
    }
    __syncthreads();

    // ---- edge row (row 3): |x(y-1) - x(y+1)| from staged fp16 values
    for (int idx = tid; idx < NCOL * CC; idx += 256) {
        int col = idx >> 6;
        int c   = idx & 63;
        float a0 = __half2float(__ushort_as_half(raw[(0 * NCOL + col) * CPAD + c]));
        float a2 = __half2float(__ushort_as_half(raw[(2 * NCOL + col) * CPAD + c]));
        raw[(3 * NCOL + col) * CPAD + c] =
            __half_as_ushort(__float2half_rn(fabsf(a0 - a2)));
    }
    __syncthreads();   // raw tile final — no more barriers until epilogue

    float acc[4][4];
#pragma unroll
    for (int ni = 0; ni < 4; ni++)
#pragma unroll
        for (int r = 0; r < 4; r++) acc[ni][r] = 0.0f;

    const int px0 = ((wid >> 2) & 1) * 16;
    const int oc0 = ((wid >> 1) & 1) * 32;
    const int kc0 = (wid & 1) * 32;
    const int o2w = (wid >> 1) & 1;
    const int k2w = wid & 1;
    const int arow_lane = lane & 15;
    const int acol_lane = (lane >> 4) * 8;

    // per-warp B table base: [tap][o2][k2][np][ki][lane]
    const uint4* Bw = g_Bf + o2w * 256 + k2w * 128 + lane;

#pragma unroll
    for (int t = 0; t < 10; t++) {
        const int dy = (t < 9) ? t / 3 : 3;
        const int dx = (t < 9) ? t % 3 : 1;

        // ki-interleaved to keep live set small: A(ki) 4 regs + B(ki) 8 regs
#pragma unroll
        for (int ki = 0; ki < 2; ki++) {
            uint32_t A[4];
            int o = (dy * NCOL + px0 + dx + arow_lane) * CPAD
                  + kc0 + ki * 16 + acol_lane;
            LDM4(A[0], A[1], A[2], A[3], sbase + (uint32_t)(o * 2));

            uint32_t Bf[2][4];
#pragma unroll
            for (int np = 0; np < 2; np++) {
                uint4 v = __ldg(Bw + t * 512 + np * 64 + ki * 32);
                Bf[np][0] = v.x; Bf[np][1] = v.y;
                Bf[np][2] = v.z; Bf[np][3] = v.w;
            }
#pragma unroll
            for (int ni = 0; ni < 4; ni++)
                MMA(acc[ni], A, (&Bf[ni >> 1][(ni & 1) * 2]));
        }
    }

    // ---- combine K halves via smem exchange
    float* ex = (float*)(smem + EX_OFF);
    const int pair = wid >> 1;                 // (p,o) pair 0..3
    if (wid & 1) {                             // K-half 1 warps store
#pragma unroll
        for (int ni = 0; ni < 4; ni++)
            *(float4*)&ex[pair * 512 + ni * 128 + lane * 4] =
                make_float4(acc[ni][0], acc[ni][1], acc[ni][2], acc[ni][3]);
    }
    __syncthreads();

    if (!(wid & 1)) {                          // K-half 0 warps finish
#pragma unroll
        for (int ni = 0; ni < 4; ni++) {
            float4 p = *(float4*)&ex[pair * 512 + ni * 128 + lane * 4];
            const int oca = oc0 + ni * 8 + 2 * (lane & 3);
            float d0 = acc[ni][0] + p.x;       // bias folded later (exact fp32)
            float d1 = acc[ni][1] + p.y;
            float d2 = acc[ni][2] + p.z;
            float d3 = acc[ni][3] + p.w;
            int pxg = x0 + px0 + (lane >> 2);
            size_t base = ((size_t)b * CC + oca) * (size_t)(HH * WW)
                        + (size_t)y * WW + pxg;
            g_comb[base]               = __float2half_rn(d0);
            g_comb[base + HH * WW]     = __float2half_rn(d1);
            g_comb[base + 8]           = __float2half_rn(d2);
            g_comb[base + HH * WW + 8] = __float2half_rn(d3);
            float sA = d0 + d2;
            float sB = d1 + d3;
#pragma unroll
            for (int s = 4; s < 32; s <<= 1) {
                sA += __shfl_xor_sync(0xffffffffu, sA, s);
                sB += __shfl_xor_sync(0xffffffffu, sB, s);
            }
            if (lane < 4) {
                atomicAdd(&s_red[oca], sA);
                atomicAdd(&s_red[oca + 1], sB);
            }
        }
    }
    __syncthreads();
    if (tid < CC) atomicAdd(&g_pooled[b * CC + tid], s_red[tid]);
}

// ---------------------------------------------------------------------------
// Kernel 2: SE attention. pooled mean = g_pooled/(HW) + THETA*bias (exact).
// ---------------------------------------------------------------------------
__global__ void attn_kernel(const float* __restrict__ W1, const float* __restrict__ b1,
                            const float* __restrict__ W2, const float* __restrict__ b2,
                            const float* __restrict__ bc) {
    __shared__ float sh[BB * 8];
    const int t = threadIdx.x;
    if (t < BB * 8) {
        int b = t >> 3, r = t & 7;
        float s = b1[r];
        const float inv = 1.0f / (float)(HH * WW);
#pragma unroll
        for (int c = 0; c < CC; c++)
            s += (g_pooled[b * CC + c] * inv + THETA * bc[c]) * W1[r * CC + c];
        sh[t] = fmaxf(s, 0.0f);
    }
    __syncthreads();
    for (int idx = t; idx < BB * CC; idx += 256) {
        int b = idx >> 6, o = idx & 63;
        float s = b2[o];
#pragma unroll
        for (int r = 0; r < 8; r++)
            s += sh[b * 8 + r] * W2[o * 8 + r];
        g_attn[idx] = 1.0f / (1.0f + expf(-s));
    }
}

// ---------------------------------------------------------------------------
// Kernel 3: out = (fp16 comb + THETA*bias) * attn  (float4 stores)
// ---------------------------------------------------------------------------
__global__ void scale_kernel(float* __restrict__ out, const float* __restrict__ bc) {
    int i = blockIdx.x * blockDim.x + threadIdx.x;   // float4 index
    const __half2* cb = (const __half2*)g_comb;
    __half2 h0 = cb[2 * i];
    __half2 h1 = cb[2 * i + 1];
    int bcidx = i >> 14;                 // b*64 + c
    float a  = g_attn[bcidx];
    float tb = THETA * __ldg(&bc[bcidx & 63]);
    float2 f0 = __half22float2(h0);
    float2 f1 = __half22float2(h1);
    float4 v;
    v.x = (f0.x + tb) * a;
    v.y = (f0.y + tb) * a;
    v.z = (f1.x + tb) * a;
    v.w = (f1.y + tb) * a;
    ((float4*)out)[i] = v;
}

// ---------------------------------------------------------------------------
extern "C" void kernel_launch(void* const* d_in, const int* in_sizes, int n_in,
                              void* d_out, int out_size) {
    const float* x  = (const float*)d_in[0];
    const float* Wc = (const float*)d_in[1];
    const float* bc = (const float*)d_in[2];
    const float* We = (const float*)d_in[3];
    const float* W1 = (const float*)d_in[4];
    const float* b1 = (const float*)d_in[5];
    const float* W2 = (const float*)d_in[6];
    const float* b2 = (const float*)d_in[7];
    float* out = (float*)d_out;

    cudaFuncSetAttribute(conv_kernel, cudaFuncAttributeMaxDynamicSharedMemorySize, SMEM_BYTES);

    prepack_kernel<<<24, 256>>>(Wc, We);

    dim3 grid(WW / PX, HH, BB);
    conv_kernel<<<grid, 256, SMEM_BYTES>>>(x);

    attn_kernel<<<1, 256>>>(W1, b1, W2, b2, bc);

    scale_kernel<<<(BB * CC * HH * WW / 4) / 256, 256>>>(out, bc);
}